// round 11
// baseline (speedup 1.0000x reference)
#include <cuda_runtime.h>
#include <cstdint>

#define HH 256
#define WW 256
#define BB 8
#define NGT 256
#define NPIX (HH*WW)
#define GRID 1024
#define TILES 2            // GRID*TILES == HH*BB tiles

static __device__ __constant__ float kMAXD = 362.03867196751236f; // sqrt(256^2+256^2)
#define EPSF 1e-6f

// Persistent scratch (zero at module load; finalize restores zeros after use)
__device__ float g_S[BB*NGT];   // per-(b,j) sum over pixels of (wd+eps)^-9
__device__ float g_t1[BB];      // per-b sum p*min_d
__device__ float g_np[BB];      // per-b sum p
__device__ unsigned int g_done; // block-completion ticket

typedef unsigned long long u64;

__device__ __forceinline__ float sqrt_approx(float x) {
    float r; asm("sqrt.approx.f32 %0, %1;" : "=f"(r) : "f"(x)); return r;
}
__device__ __forceinline__ float lg2_approx(float x) {
    float r; asm("lg2.approx.f32 %0, %1;" : "=f"(r) : "f"(x)); return r;
}
__device__ __forceinline__ float ex2_approx(float x) {
    float r; asm("ex2.approx.f32 %0, %1;" : "=f"(r) : "f"(x)); return r;
}
// ---- packed f32x2 helpers (Blackwell FFMA2 path, PTX-only) ----
__device__ __forceinline__ u64 pk2(float x, float y) {
    u64 r; asm("mov.b64 %0, {%1, %2};" : "=l"(r) : "f"(x), "f"(y)); return r;
}
__device__ __forceinline__ float lo2(u64 v) {
    float r; asm("{ .reg .f32 h; mov.b64 {%0, h}, %1; }" : "=f"(r) : "l"(v)); return r;
}
__device__ __forceinline__ float hi2(u64 v) {
    float r; asm("{ .reg .f32 l; mov.b64 {l, %0}, %1; }" : "=f"(r) : "l"(v)); return r;
}
__device__ __forceinline__ u64 ffma2(u64 a, u64 b, u64 c) {
    u64 d; asm("fma.rn.f32x2 %0, %1, %2, %3;" : "=l"(d) : "l"(a), "l"(b), "l"(c)); return d;
}
__device__ __forceinline__ u64 fmul2(u64 a, u64 b) {
    u64 d; asm("mul.rn.f32x2 %0, %1, %2;" : "=l"(d) : "l"(a), "l"(b)); return d;
}
__device__ __forceinline__ u64 fadd2(u64 a, u64 b) {
    u64 d; asm("add.rn.f32x2 %0, %1, %2;" : "=l"(d) : "l"(a), "l"(b)); return d;
}
// bithack reciprocal seed from NEGATIVE input (ntt < 0):
// seed = 0x7EF311C3 - bits(tt) = 0xFEF311C3 - bits(ntt)  (mod 2^32), per half
__device__ __forceinline__ u64 rcp_seed_from_neg(u64 ntt) {
    uint32_t bl = (uint32_t)ntt;
    uint32_t bh = (uint32_t)(ntt >> 32);
    uint32_t sl = 0xFEF311C3u - bl;
    uint32_t sh = 0xFEF311C3u - bh;
    return ((u64)sh << 32) | (u64)sl;
}

// -------------------------------------------------------------------
// Single fused kernel, persistent-ish: GRID=1024 blocks, each handles 2
// (row,b) tiles -> exactly one wave at 8 blocks/SM (regs capped to 32).
// Within a tile: thread t = gt point j (term2) and pixel x=t (term1),
// one interleaved loop, 2 pixels / 2 gts per iteration in packed f32x2.
// Last block (ticket) reduces scratch to out[0] and re-zeroes it.
__global__ void __launch_bounds__(256, 8) k_fused(const float* __restrict__ prob,
                                                  const float* __restrict__ gt,
                                                  float* __restrict__ out) {
    __shared__ ulonglong2 s_a[128];  // .x=(-p,-p') .y=(-c,-c') per pixel pair
    __shared__ ulonglong2 s_b[128];  // .x=(-xj,-xj') .y=(dy2e,dy2e') per gt pair
    __shared__ float s_c[8], s_p[8];
    __shared__ unsigned int s_last;

    const int t = threadIdx.x;

#pragma unroll 1
    for (int tile = 0; tile < TILES; tile++) {
        const int tau = blockIdx.x + tile * GRID;
        const int row = tau & (HH - 1);
        const int b   = tau >> 8;

        // gt point j = t
        float2 g  = ((const float2*)gt)[b*NGT + t];   // (y_j, x_j)
        float dy  = (float)row - g.x;
        float dy2e = fmaf(dy, dy, 1e-18f);

        // pixel x = t
        float p = prob[(b*HH + row)*WW + t];
        float c = fmaf(-p, kMAXD, kMAXD) + EPSF;      // (1-p)*M + eps

        {   // interleaved pair layout, negated where the loop wants negatives
            float* fa = (float*)s_a;
            float* fb = (float*)s_b;
            int base = (t >> 1) * 4 + (t & 1);
            fa[base]     = -p;
            fa[base + 2] = -c;
            fb[base]     = -g.y;
            fb[base + 2] = dy2e;
        }
        __syncthreads();

        const u64 one2  = pk2(1.0f, 1.0f);
        const u64 two2  = pk2(2.0f, 2.0f);
        const u64 dy2s  = pk2(dy2e, dy2e);
        const float xf  = (float)t;
        const u64 xf2   = pk2(xf, xf);

        u64 dxA  = pk2(0.0f - g.y, 1.0f - g.y);       // (x - xj) for x=0,1
        u64 acc2 = pk2(0.0f, 0.0f);
        float mlo = 3.4e38f, mhi = 3.4e38f;

#pragma unroll 4
        for (int i = 0; i < 128; i++) {
            ulonglong2 qa = s_a[i];                   // LDS.128 broadcast
            ulonglong2 qb = s_b[i];                   // LDS.128 broadcast
            // ---- term2 (2 pixels) ----
            u64 d2p = ffma2(dxA, dxA, dy2s);
            u64 dp  = pk2(sqrt_approx(lo2(d2p)), sqrt_approx(hi2(d2p))); // 2x MUFU
            u64 ntt = ffma2(qa.x, dp, qa.y);          // -(p*d + c)
            u64 y0  = rcp_seed_from_neg(ntt);         // ~1/tt (2x IADD)
            u64 e1  = ffma2(ntt, y0, one2);           // 1 - tt*y0
            u64 y1  = ffma2(y0, e1, y0);
            u64 e2  = fmul2(e1, e1);
            u64 y2  = ffma2(y1, e2, y1);              // 1/tt, err ~ d^4
            u64 i2  = fmul2(y2, y2);
            u64 i4  = fmul2(i2, i2);
            u64 i8  = fmul2(i4, i4);
            acc2 = ffma2(i8, y2, acc2);               // += tt^-9
            dxA  = fadd2(dxA, two2);
            // ---- term1 (2 gt points) ----
            u64 dxB  = fadd2(xf2, qb.x);              // x - xj
            u64 cand = ffma2(dxB, dxB, qb.y);
            mlo = fminf(mlo, lo2(cand));
            mhi = fminf(mhi, hi2(cand));
        }

        atomicAdd(&g_S[b*NGT + t], lo2(acc2) + hi2(acc2));

        float m = fminf(mlo, mhi);
        float cterm = p * sqrt_approx(m);
        float pr = p;
#pragma unroll
        for (int o = 16; o; o >>= 1) {
            cterm += __shfl_down_sync(0xFFFFFFFFu, cterm, o);
            pr    += __shfl_down_sync(0xFFFFFFFFu, pr, o);
        }
        if ((t & 31) == 0) { s_c[t >> 5] = cterm; s_p[t >> 5] = pr; }
        __syncthreads();
        if (t == 0) {
            float C = 0.0f, P = 0.0f;
#pragma unroll
            for (int i = 0; i < 8; i++) { C += s_c[i]; P += s_p[i]; }
            atomicAdd(&g_t1[b], C);
            atomicAdd(&g_np[b], P);
        }
        // s_a/s_b rewrites in the next tile are safe: every thread passed the
        // __syncthreads above, so all reads of this tile's smem are done.
    }

    // ---- completion ticket ----
    __threadfence();                 // release this block's global atomics
    __syncthreads();
    if (t == 0) {
        s_last = (atomicAdd(&g_done, 1u) == (GRID - 1)) ? 1u : 0u;
    }
    __syncthreads();
    if (s_last == 0u) return;

    // ---- finalize (last block only) ----
    __threadfence();                 // acquire: all blocks' atomics visible
    __shared__ float sred[8];
    __shared__ float st1[8];
    const float invA = -1.0f / 9.0f;

    float s = 0.0f;
#pragma unroll
    for (int bb = 0; bb < BB; bb++) {
        float mm = __ldcg(&g_S[bb*NGT + t]) * (1.0f / (float)NPIX);
        s += ex2_approx(lg2_approx(mm) * invA);   // mm^(-1/9)
    }
    if (t < BB) st1[t] = __ldcg(&g_t1[t]) / (__ldcg(&g_np[t]) + EPSF);

#pragma unroll
    for (int o = 16; o; o >>= 1) s += __shfl_down_sync(0xFFFFFFFFu, s, o);
    if ((t & 31) == 0) sred[t >> 5] = s;
    __syncthreads();

    // re-zero scratch + ticket for the next graph replay
#pragma unroll
    for (int bb = 0; bb < BB; bb++) g_S[bb*NGT + t] = 0.0f;
    if (t < BB) { g_t1[t] = 0.0f; g_np[t] = 0.0f; }
    if (t == 0) g_done = 0u;

    if (t == 0) {
        float T2 = 0.0f;
#pragma unroll
        for (int i = 0; i < 8; i++) T2 += sred[i];
        T2 *= (1.0f / (float)(BB * NGT));
        float T1 = 0.0f;
#pragma unroll
        for (int bb = 0; bb < BB; bb++) T1 += st1[bb];
        T1 *= (1.0f / (float)BB);
        out[0] = T1 + T2;
    }
}

// -------------------------------------------------------------------
extern "C" void kernel_launch(void* const* d_in, const int* in_sizes, int n_in,
                              void* d_out, int out_size) {
    const float* prob = (const float*)d_in[0];   // (B,1,H,W) f32
    const float* gt   = (const float*)d_in[1];   // (B,NGT,2) f32
    float* out = (float*)d_out;

    k_fused<<<GRID, 256>>>(prob, gt, out);
}

// round 12
// speedup vs baseline: 1.0414x; 1.0414x over previous
#include <cuda_runtime.h>
#include <cstdint>

#define HH 256
#define WW 256
#define BB 8
#define NGT 256
#define NPIX (HH*WW)
#define NBLK (HH*BB)

static __device__ __constant__ float kMAXD = 362.03867196751236f; // sqrt(256^2+256^2)
#define EPSF 1e-6f

// Persistent scratch (zero at module load; finalize restores zeros after use)
__device__ float g_S[BB*NGT];   // per-(b,j) sum over pixels of (wd+eps)^-9
__device__ float g_t1[BB];      // per-b sum p*min_d
__device__ float g_np[BB];      // per-b sum p
__device__ unsigned int g_done; // block-completion ticket

typedef unsigned long long u64;

__device__ __forceinline__ float sqrt_approx(float x) {
    float r; asm("sqrt.approx.f32 %0, %1;" : "=f"(r) : "f"(x)); return r;
}
__device__ __forceinline__ float rcp_approx(float x) {
    float r; asm("rcp.approx.f32 %0, %1;" : "=f"(r) : "f"(x)); return r;
}
__device__ __forceinline__ float lg2_approx(float x) {
    float r; asm("lg2.approx.f32 %0, %1;" : "=f"(r) : "f"(x)); return r;
}
__device__ __forceinline__ float ex2_approx(float x) {
    float r; asm("ex2.approx.f32 %0, %1;" : "=f"(r) : "f"(x)); return r;
}
// ---- packed f32x2 helpers (Blackwell FFMA2 path, PTX-only) ----
__device__ __forceinline__ u64 pk2(float x, float y) {
    u64 r; asm("mov.b64 %0, {%1, %2};" : "=l"(r) : "f"(x), "f"(y)); return r;
}
__device__ __forceinline__ float lo2(u64 v) {
    float r; asm("{ .reg .f32 h; mov.b64 {%0, h}, %1; }" : "=f"(r) : "l"(v)); return r;
}
__device__ __forceinline__ float hi2(u64 v) {
    float r; asm("{ .reg .f32 l; mov.b64 {l, %0}, %1; }" : "=f"(r) : "l"(v)); return r;
}
__device__ __forceinline__ u64 ffma2(u64 a, u64 b, u64 c) {
    u64 d; asm("fma.rn.f32x2 %0, %1, %2, %3;" : "=l"(d) : "l"(a), "l"(b), "l"(c)); return d;
}
__device__ __forceinline__ u64 fmul2(u64 a, u64 b) {
    u64 d; asm("mul.rn.f32x2 %0, %1, %2;" : "=l"(d) : "l"(a), "l"(b)); return d;
}
__device__ __forceinline__ u64 fadd2(u64 a, u64 b) {
    u64 d; asm("add.rn.f32x2 %0, %1, %2;" : "=l"(d) : "l"(a), "l"(b)); return d;
}
// bithack reciprocal seed from NEGATIVE input (ntt < 0):
// seed = 0x7EF311C3 - bits(tt) = 0xFEF311C3 - bits(ntt)  (mod 2^32), per half
__device__ __forceinline__ u64 rcp_seed_from_neg(u64 ntt) {
    uint32_t bl = (uint32_t)ntt;
    uint32_t bh = (uint32_t)(ntt >> 32);
    uint32_t sl = 0xFEF311C3u - bl;
    uint32_t sh = 0xFEF311C3u - bh;
    return ((u64)sh << 32) | (u64)sl;
}

// -------------------------------------------------------------------
// Single fused kernel. Block = (row, b), 256 threads (grid 2048 — R10 shape).
// Thread t: gt point j=t (term2) AND pixel x=t (term1), one interleaved loop,
// 2 pixels / 2 gt points per iteration in packed f32x2.
// Reciprocal alternates per iteration to balance FMA and MUFU pipes:
//   even pair: ALU bithack seed + 2 packed Newton steps (FMA-heavy)
//   odd  pair: direct MUFU rcp.approx (MUFU-heavy; accumulates -t^-9)
// Last block (ticket) reduces scratch to out[0] and re-zeroes it.
__global__ void __launch_bounds__(256, 6) k_fused(const float* __restrict__ prob,
                                                  const float* __restrict__ gt,
                                                  float* __restrict__ out) {
    __shared__ ulonglong2 s_a[128];  // .x=(-p,-p') .y=(-c,-c') per pixel pair
    __shared__ ulonglong2 s_b[128];  // .x=(-xj,-xj') .y=(dy2e,dy2e') per gt pair
    __shared__ float s_c[8], s_p[8];
    __shared__ unsigned int s_last;

    const int row = blockIdx.x;
    const int b   = blockIdx.y;
    const int t   = threadIdx.x;

    // gt point j = t
    float2 g  = ((const float2*)gt)[b*NGT + t];   // (y_j, x_j)
    float dy  = (float)row - g.x;
    float dy2e = fmaf(dy, dy, 1e-18f);

    // pixel x = t
    float p = prob[(b*HH + row)*WW + t];
    float c = fmaf(-p, kMAXD, kMAXD) + EPSF;      // (1-p)*M + eps

    {   // interleaved pair layout, negated where the loop wants negatives
        float* fa = (float*)s_a;
        float* fb = (float*)s_b;
        int base = (t >> 1) * 4 + (t & 1);
        fa[base]     = -p;
        fa[base + 2] = -c;
        fb[base]     = -g.y;
        fb[base + 2] = dy2e;
    }
    __syncthreads();

    const u64 one2  = pk2(1.0f, 1.0f);
    const u64 two2  = pk2(2.0f, 2.0f);
    const u64 dy2s  = pk2(dy2e, dy2e);
    const float xf  = (float)t;
    const u64 xf2   = pk2(xf, xf);

    u64 dxA  = pk2(0.0f - g.y, 1.0f - g.y);       // (x - xj) for x=0,1
    u64 accN = pk2(0.0f, 0.0f);                    // Newton path: +t^-9
    u64 accR = pk2(0.0f, 0.0f);                    // rcp path:    -t^-9
    float mlo = 3.4e38f, mhi = 3.4e38f;

#pragma unroll 2
    for (int i = 0; i < 128; i += 2) {
        // ======== pair A (pixels 2i,2i+1): bithack + Newton, FMA-heavy ========
        {
            ulonglong2 qa = s_a[i];                // LDS.128 broadcast
            ulonglong2 qb = s_b[i];
            u64 d2p = ffma2(dxA, dxA, dy2s);
            u64 dp  = pk2(sqrt_approx(lo2(d2p)), sqrt_approx(hi2(d2p))); // 2x MUFU
            u64 ntt = ffma2(qa.x, dp, qa.y);       // -(p*d + c)
            u64 y0  = rcp_seed_from_neg(ntt);      // ~ +1/t (2x IADD, ALU)
            u64 e1  = ffma2(ntt, y0, one2);        // 1 - t*y0
            u64 y1  = ffma2(y0, e1, y0);
            u64 e2  = fmul2(e1, e1);
            u64 y2  = ffma2(y1, e2, y1);           // +1/t, err ~ d^4
            u64 i2  = fmul2(y2, y2);
            u64 i4  = fmul2(i2, i2);
            u64 i8  = fmul2(i4, i4);
            accN = ffma2(i8, y2, accN);            // += t^-9
            dxA  = fadd2(dxA, two2);
            u64 dxB  = fadd2(xf2, qb.x);
            u64 cand = ffma2(dxB, dxB, qb.y);
            mlo = fminf(mlo, lo2(cand));
            mhi = fminf(mhi, hi2(cand));
        }
        // ======== pair B (pixels 2i+2,2i+3): direct MUFU rcp, MUFU-heavy ========
        {
            ulonglong2 qa = s_a[i + 1];
            ulonglong2 qb = s_b[i + 1];
            u64 d2p = ffma2(dxA, dxA, dy2s);
            u64 dp  = pk2(sqrt_approx(lo2(d2p)), sqrt_approx(hi2(d2p))); // 2x MUFU
            u64 ntt = ffma2(qa.x, dp, qa.y);       // -(t)
            u64 yv  = pk2(rcp_approx(lo2(ntt)), rcp_approx(hi2(ntt)));   // 2x MUFU, -(1/t)
            u64 i2  = fmul2(yv, yv);               // +t^-2
            u64 i4  = fmul2(i2, i2);
            u64 i8  = fmul2(i4, i4);               // +t^-8
            accR = ffma2(i8, yv, accR);            // += -(t^-9)
            dxA  = fadd2(dxA, two2);
            u64 dxB  = fadd2(xf2, qb.x);
            u64 cand = ffma2(dxB, dxB, qb.y);
            mlo = fminf(mlo, lo2(cand));
            mhi = fminf(mhi, hi2(cand));
        }
    }

    float accsum = (lo2(accN) + hi2(accN)) - (lo2(accR) + hi2(accR));
    atomicAdd(&g_S[b*NGT + t], accsum);

    float m = fminf(mlo, mhi);
    float cterm = p * sqrt_approx(m);
    float pr = p;
#pragma unroll
    for (int o = 16; o; o >>= 1) {
        cterm += __shfl_down_sync(0xFFFFFFFFu, cterm, o);
        pr    += __shfl_down_sync(0xFFFFFFFFu, pr, o);
    }
    if ((t & 31) == 0) { s_c[t >> 5] = cterm; s_p[t >> 5] = pr; }
    __syncthreads();
    if (t == 0) {
        float C = 0.0f, P = 0.0f;
#pragma unroll
        for (int i = 0; i < 8; i++) { C += s_c[i]; P += s_p[i]; }
        atomicAdd(&g_t1[b], C);
        atomicAdd(&g_np[b], P);
    }

    // ---- completion ticket: release this block's atomics, grab ticket ----
    __threadfence();
    __syncthreads();
    if (t == 0) {
        s_last = (atomicAdd(&g_done, 1u) == (NBLK - 1)) ? 1u : 0u;
    }
    __syncthreads();
    if (s_last == 0u) return;

    // ---- finalize (only the last block) ----
    __threadfence();                 // acquire: all other blocks' atomics visible
    __shared__ float sred[8];
    __shared__ float st1[8];
    const float invA = -1.0f / 9.0f;

    float s = 0.0f;
#pragma unroll
    for (int bb = 0; bb < BB; bb++) {
        float mm = __ldcg(&g_S[bb*NGT + t]) * (1.0f / (float)NPIX);
        s += ex2_approx(lg2_approx(mm) * invA);   // mm^(-1/9)
    }
    if (t < BB) st1[t] = __ldcg(&g_t1[t]) / (__ldcg(&g_np[t]) + EPSF);

#pragma unroll
    for (int o = 16; o; o >>= 1) s += __shfl_down_sync(0xFFFFFFFFu, s, o);
    if ((t & 31) == 0) sred[t >> 5] = s;
    __syncthreads();

    // re-zero scratch + ticket for the next graph replay
#pragma unroll
    for (int bb = 0; bb < BB; bb++) g_S[bb*NGT + t] = 0.0f;
    if (t < BB) { g_t1[t] = 0.0f; g_np[t] = 0.0f; }
    if (t == 0) g_done = 0u;

    if (t == 0) {
        float T2 = 0.0f;
#pragma unroll
        for (int i = 0; i < 8; i++) T2 += sred[i];
        T2 *= (1.0f / (float)(BB * NGT));
        float T1 = 0.0f;
#pragma unroll
        for (int bb = 0; bb < BB; bb++) T1 += st1[bb];
        T1 *= (1.0f / (float)BB);
        out[0] = T1 + T2;
    }
}

// -------------------------------------------------------------------
extern "C" void kernel_launch(void* const* d_in, const int* in_sizes, int n_in,
                              void* d_out, int out_size) {
    const float* prob = (const float*)d_in[0];   // (B,1,H,W) f32
    const float* gt   = (const float*)d_in[1];   // (B,NGT,2) f32
    float* out = (float*)d_out;

    dim3 grid(HH, BB);
    k_fused<<<grid, 256>>>(prob, gt, out);
}

// round 14
// speedup vs baseline: 1.1032x; 1.0594x over previous
#include <cuda_runtime.h>
#include <cstdint>

#define HH 256
#define WW 256
#define BB 8
#define NGT 256
#define NPIX (HH*WW)
#define NBLK (HH*BB)

static __device__ __constant__ float kMAXD = 362.03867196751236f; // sqrt(256^2+256^2)
#define EPSF 1e-6f

// Persistent scratch (zero at module load; finalize restores zeros after use)
__device__ float g_S[BB*NGT];   // per-(b,j) sum over pixels of (wd+eps)^-9
__device__ float g_t1[BB];      // per-b sum p*min_d
__device__ float g_np[BB];      // per-b sum p
__device__ unsigned int g_done; // block-completion ticket

typedef unsigned long long u64;

__device__ __forceinline__ float sqrt_approx(float x) {
    float r; asm("sqrt.approx.f32 %0, %1;" : "=f"(r) : "f"(x)); return r;
}
__device__ __forceinline__ float lg2_approx(float x) {
    float r; asm("lg2.approx.f32 %0, %1;" : "=f"(r) : "f"(x)); return r;
}
__device__ __forceinline__ float ex2_approx(float x) {
    float r; asm("ex2.approx.f32 %0, %1;" : "=f"(r) : "f"(x)); return r;
}
// ---- packed f32x2 helpers ----
__device__ __forceinline__ u64 pk2(float x, float y) {
    u64 r; asm("mov.b64 %0, {%1, %2};" : "=l"(r) : "f"(x), "f"(y)); return r;
}
__device__ __forceinline__ float lo2(u64 v) {
    float r; asm("{ .reg .f32 h; mov.b64 {%0, h}, %1; }" : "=f"(r) : "l"(v)); return r;
}
__device__ __forceinline__ float hi2(u64 v) {
    float r; asm("{ .reg .f32 l; mov.b64 {l, %0}, %1; }" : "=f"(r) : "l"(v)); return r;
}
__device__ __forceinline__ u64 ffma2(u64 a, u64 b, u64 c) {
    u64 d; asm("fma.rn.f32x2 %0, %1, %2, %3;" : "=l"(d) : "l"(a), "l"(b), "l"(c)); return d;
}
__device__ __forceinline__ u64 fmul2(u64 a, u64 b) {
    u64 d; asm("mul.rn.f32x2 %0, %1, %2;" : "=l"(d) : "l"(a), "l"(b)); return d;
}
__device__ __forceinline__ u64 fadd2(u64 a, u64 b) {
    u64 d; asm("add.rn.f32x2 %0, %1, %2;" : "=l"(d) : "l"(a), "l"(b)); return d;
}
// bithack reciprocal seed from NEGATIVE input (ntt < 0):
// seed = 0x7EF311C3 - bits(tt) = 0xFEF311C3 - bits(ntt)  (mod 2^32), per half
__device__ __forceinline__ u64 rcp_seed_from_neg(u64 ntt) {
    uint32_t bl = (uint32_t)ntt;
    uint32_t bh = (uint32_t)(ntt >> 32);
    uint32_t sl = 0xFEF311C3u - bl;
    uint32_t sh = 0xFEF311C3u - bh;
    return ((u64)sh << 32) | (u64)sl;
}

// -------------------------------------------------------------------
// Single fused kernel. Block = (row, b), 256 threads, grid 2048 (R10 shape).
// Thread t: gt point j=t (term2) AND pixel x=t (term1), one interleaved loop,
// 2 pixels / 2 gt points per iteration in packed f32x2.
// term1 uses the expanded form  (x-xj)^2 + dy2 = x^2 + (B_j*x + A_j)
// with B_j=-2xj, A_j=xj^2+dy2 precomputed -> 1 ffma2 + 2 FMNMX per pair.
// Last block (ticket) reduces scratch to out[0] and re-zeroes it.
__global__ void __launch_bounds__(256, 8) k_fused(const float* __restrict__ prob,
                                                  const float* __restrict__ gt,
                                                  float* __restrict__ out) {
    __shared__ ulonglong2 s_a[128];  // .x=(-p,-p') .y=(-c,-c') per pixel pair
    __shared__ ulonglong2 s_b[128];  // .x=(B,B')   .y=(A,A')   per gt pair
    __shared__ float s_c[8], s_p[8];
    __shared__ unsigned int s_last;

    const int row = blockIdx.x;
    const int b   = blockIdx.y;
    const int t   = threadIdx.x;

    // gt point j = t
    float2 g  = ((const float2*)gt)[b*NGT + t];   // (y_j, x_j)
    float dy  = (float)row - g.x;
    float dy2e = fmaf(dy, dy, 1e-18f);

    // pixel x = t
    float p = prob[(b*HH + row)*WW + t];
    float c = fmaf(-p, kMAXD, kMAXD) + EPSF;      // (1-p)*M + eps

    {   // interleaved pair layout
        float* fa = (float*)s_a;
        float* fb = (float*)s_b;
        int base = (t >> 1) * 4 + (t & 1);
        fa[base]     = -p;
        fa[base + 2] = -c;
        fb[base]     = -2.0f * g.y;               // B_j
        fb[base + 2] = fmaf(g.y, g.y, dy2e);      // A_j = xj^2 + dy^2
    }
    __syncthreads();

    const u64 one2  = pk2(1.0f, 1.0f);
    const u64 two2  = pk2(2.0f, 2.0f);
    const u64 dy2s  = pk2(dy2e, dy2e);
    const float xf  = (float)t;
    const u64 xf2   = pk2(xf, xf);

    u64 dxA  = pk2(0.0f - g.y, 1.0f - g.y);       // (x - xj) for x=0,1
    u64 acc2 = pk2(0.0f, 0.0f);
    float mlo = 3.4e38f, mhi = 3.4e38f;           // running min of B*x+A

#pragma unroll 4
    for (int i = 0; i < 128; i++) {
        ulonglong2 qa = s_a[i];                   // LDS.128 broadcast
        ulonglong2 qb = s_b[i];                   // LDS.128 broadcast
        // ---- term2 (2 pixels) ----
        u64 d2p = ffma2(dxA, dxA, dy2s);
        u64 dp  = pk2(sqrt_approx(lo2(d2p)), sqrt_approx(hi2(d2p))); // 2x MUFU
        u64 ntt = ffma2(qa.x, dp, qa.y);          // -(p*d + c)
        u64 y0  = rcp_seed_from_neg(ntt);         // ~1/t (2x IADD, ALU)
        u64 e1  = ffma2(ntt, y0, one2);           // 1 - t*y0
        u64 y1  = ffma2(y0, e1, y0);
        u64 e2  = fmul2(e1, e1);
        u64 y2  = ffma2(y1, e2, y1);              // 1/t, err ~ d^4
        u64 i2  = fmul2(y2, y2);
        u64 i4  = fmul2(i2, i2);
        u64 i8  = fmul2(i4, i4);
        acc2 = ffma2(i8, y2, acc2);               // += t^-9
        dxA  = fadd2(dxA, two2);
        // ---- term1 (2 gt points): B*x + A, scalar min on halves ----
        u64 cand = ffma2(qb.x, xf2, qb.y);
        mlo = fminf(mlo, lo2(cand));
        mhi = fminf(mhi, hi2(cand));
    }

    atomicAdd(&g_S[b*NGT + t], lo2(acc2) + hi2(acc2));

    float m = fminf(mlo, mhi) + xf * xf;          // add x^2 once
    m = fmaxf(m, 1e-12f);                         // cancellation guard
    float cterm = p * sqrt_approx(m);
    float pr = p;
#pragma unroll
    for (int o = 16; o; o >>= 1) {
        cterm += __shfl_down_sync(0xFFFFFFFFu, cterm, o);
        pr    += __shfl_down_sync(0xFFFFFFFFu, pr, o);
    }
    if ((t & 31) == 0) { s_c[t >> 5] = cterm; s_p[t >> 5] = pr; }
    __syncthreads();
    if (t == 0) {
        float C = 0.0f, P = 0.0f;
#pragma unroll
        for (int i = 0; i < 8; i++) { C += s_c[i]; P += s_p[i]; }
        atomicAdd(&g_t1[b], C);
        atomicAdd(&g_np[b], P);
    }

    // ---- completion ticket: release this block's atomics, grab ticket ----
    __threadfence();
    __syncthreads();
    if (t == 0) {
        s_last = (atomicAdd(&g_done, 1u) == (NBLK - 1)) ? 1u : 0u;
    }
    __syncthreads();
    if (s_last == 0u) return;

    // ---- finalize (only the last block) ----
    __threadfence();                 // acquire: all other blocks' atomics visible
    __shared__ float sred[8];
    __shared__ float st1[8];
    const float invA = -1.0f / 9.0f;

    float s = 0.0f;
#pragma unroll
    for (int bb = 0; bb < BB; bb++) {
        float mm = __ldcg(&g_S[bb*NGT + t]) * (1.0f / (float)NPIX);
        s += ex2_approx(lg2_approx(mm) * invA);   // mm^(-1/9)
    }
    if (t < BB) st1[t] = __ldcg(&g_t1[t]) / (__ldcg(&g_np[t]) + EPSF);

#pragma unroll
    for (int o = 16; o; o >>= 1) s += __shfl_down_sync(0xFFFFFFFFu, s, o);
    if ((t & 31) == 0) sred[t >> 5] = s;
    __syncthreads();

    // re-zero scratch + ticket for the next graph replay
#pragma unroll
    for (int bb = 0; bb < BB; bb++) g_S[bb*NGT + t] = 0.0f;
    if (t < BB) { g_t1[t] = 0.0f; g_np[t] = 0.0f; }
    if (t == 0) g_done = 0u;

    if (t == 0) {
        float T2 = 0.0f;
#pragma unroll
        for (int i = 0; i < 8; i++) T2 += sred[i];
        T2 *= (1.0f / (float)(BB * NGT));
        float T1 = 0.0f;
#pragma unroll
        for (int bb = 0; bb < BB; bb++) T1 += st1[bb];
        T1 *= (1.0f / (float)BB);
        out[0] = T1 + T2;
    }
}

// -------------------------------------------------------------------
extern "C" void kernel_launch(void* const* d_in, const int* in_sizes, int n_in,
                              void* d_out, int out_size) {
    const float* prob = (const float*)d_in[0];   // (B,1,H,W) f32
    const float* gt   = (const float*)d_in[1];   // (B,NGT,2) f32
    float* out = (float*)d_out;

    dim3 grid(HH, BB);
    k_fused<<<grid, 256>>>(prob, gt, out);
}

// round 16
// speedup vs baseline: 1.1313x; 1.0254x over previous
#include <cuda_runtime.h>
#include <cstdint>

#define HH 256
#define WW 256
#define BB 8
#define NGT 256
#define NPIX (HH*WW)
#define NBLK (HH*BB)

static __device__ __constant__ float kMAXD = 362.03867196751236f; // sqrt(256^2+256^2)
#define EPSF 1e-6f

// Persistent scratch (zero at module load; finalize restores zeros after use)
__device__ float g_S[BB*NGT];   // per-(b,j) sum over pixels of (wd+eps)^-9
__device__ float g_t1[BB];      // per-b sum p*min_d
__device__ float g_np[BB];      // per-b sum p
__device__ unsigned int g_done; // block-completion ticket

typedef unsigned long long u64;

__device__ __forceinline__ float sqrt_approx(float x) {
    float r; asm("sqrt.approx.f32 %0, %1;" : "=f"(r) : "f"(x)); return r;
}
__device__ __forceinline__ float lg2_approx(float x) {
    float r; asm("lg2.approx.f32 %0, %1;" : "=f"(r) : "f"(x)); return r;
}
__device__ __forceinline__ float ex2_approx(float x) {
    float r; asm("ex2.approx.f32 %0, %1;" : "=f"(r) : "f"(x)); return r;
}
// ---- packed f32x2 helpers ----
__device__ __forceinline__ u64 pk2(float x, float y) {
    u64 r; asm("mov.b64 %0, {%1, %2};" : "=l"(r) : "f"(x), "f"(y)); return r;
}
__device__ __forceinline__ float lo2(u64 v) {
    float r; asm("{ .reg .f32 h; mov.b64 {%0, h}, %1; }" : "=f"(r) : "l"(v)); return r;
}
__device__ __forceinline__ float hi2(u64 v) {
    float r; asm("{ .reg .f32 l; mov.b64 {l, %0}, %1; }" : "=f"(r) : "l"(v)); return r;
}
__device__ __forceinline__ u64 ffma2(u64 a, u64 b, u64 c) {
    u64 d; asm("fma.rn.f32x2 %0, %1, %2, %3;" : "=l"(d) : "l"(a), "l"(b), "l"(c)); return d;
}
__device__ __forceinline__ u64 fmul2(u64 a, u64 b) {
    u64 d; asm("mul.rn.f32x2 %0, %1, %2;" : "=l"(d) : "l"(a), "l"(b)); return d;
}
__device__ __forceinline__ u64 fadd2(u64 a, u64 b) {
    u64 d; asm("add.rn.f32x2 %0, %1, %2;" : "=l"(d) : "l"(a), "l"(b)); return d;
}
// bithack reciprocal seed from NEGATIVE input (ntt < 0):
// seed = 0x7EF311C3 - bits(tt) = 0xFEF311C3 - bits(ntt)  (mod 2^32), per half
__device__ __forceinline__ u64 rcp_seed_from_neg(u64 ntt) {
    uint32_t bl = (uint32_t)ntt;
    uint32_t bh = (uint32_t)(ntt >> 32);
    uint32_t sl = 0xFEF311C3u - bl;
    uint32_t sh = 0xFEF311C3u - bh;
    return ((u64)sh << 32) | (u64)sl;
}

// -------------------------------------------------------------------
// Single fused kernel. Block = (row, b), 256 threads, grid 2048.
// Thread t: gt point j=t (term2) AND pixel x=t (term1), one interleaved loop,
// 2 pixels / 2 gt points per iteration in packed f32x2.
// Reciprocal: ALU bithack seed + ONE 2nd-order Newton step (3 packed FMAs).
// term1: expanded form min_j[(x-xj)^2+dy2] = x^2 + min_j[B_j*x + A_j].
// Last block (ticket) reduces scratch to out[0] and re-zeroes it.
__global__ void __launch_bounds__(256, 8) k_fused(const float* __restrict__ prob,
                                                  const float* __restrict__ gt,
                                                  float* __restrict__ out) {
    __shared__ ulonglong2 s_a[128];  // .x=(-p,-p') .y=(-c,-c') per pixel pair
    __shared__ ulonglong2 s_b[128];  // .x=(B,B')   .y=(A,A')   per gt pair
    __shared__ float s_c[8], s_p[8];
    __shared__ unsigned int s_last;

    const int row = blockIdx.x;
    const int b   = blockIdx.y;
    const int t   = threadIdx.x;

    // gt point j = t
    float2 g  = ((const float2*)gt)[b*NGT + t];   // (y_j, x_j)
    float dy  = (float)row - g.x;
    float dy2e = fmaf(dy, dy, 1e-18f);

    // pixel x = t
    float p = prob[(b*HH + row)*WW + t];
    float c = fmaf(-p, kMAXD, kMAXD) + EPSF;      // (1-p)*M + eps

    {   // interleaved pair layout
        float* fa = (float*)s_a;
        float* fb = (float*)s_b;
        int base = (t >> 1) * 4 + (t & 1);
        fa[base]     = -p;
        fa[base + 2] = -c;
        fb[base]     = -2.0f * g.y;               // B_j
        fb[base + 2] = fmaf(g.y, g.y, dy2e);      // A_j = xj^2 + dy^2
    }
    __syncthreads();

    const u64 one2  = pk2(1.0f, 1.0f);
    const u64 two2  = pk2(2.0f, 2.0f);
    const u64 dy2s  = pk2(dy2e, dy2e);
    const float xf  = (float)t;
    const u64 xf2   = pk2(xf, xf);

    u64 dxA  = pk2(0.0f - g.y, 1.0f - g.y);       // (x - xj) for x=0,1
    u64 acc2 = pk2(0.0f, 0.0f);
    float mlo = 3.4e38f, mhi = 3.4e38f;           // running min of B*x+A

#pragma unroll 8
    for (int i = 0; i < 128; i++) {
        ulonglong2 qa = s_a[i];                   // LDS.128 broadcast
        ulonglong2 qb = s_b[i];                   // LDS.128 broadcast
        // ---- term2 (2 pixels) ----
        u64 d2p = ffma2(dxA, dxA, dy2s);
        u64 dp  = pk2(sqrt_approx(lo2(d2p)), sqrt_approx(hi2(d2p))); // 2x MUFU
        u64 ntt = ffma2(qa.x, dp, qa.y);          // -(p*d + c)
        u64 y0  = rcp_seed_from_neg(ntt);         // ~1/t (2x IADD, ALU)
        u64 e1  = ffma2(ntt, y0, one2);           // e = 1 - t*y0
        u64 uu  = ffma2(e1, e1, e1);              // e + e^2
        u64 y2  = ffma2(y0, uu, y0);              // y0(1+e+e^2) ~ 1/t, err ~ e^3
        u64 i2  = fmul2(y2, y2);
        u64 i4  = fmul2(i2, i2);
        u64 i8  = fmul2(i4, i4);
        acc2 = ffma2(i8, y2, acc2);               // += t^-9
        dxA  = fadd2(dxA, two2);
        // ---- term1 (2 gt points): B*x + A, scalar min on halves ----
        u64 cand = ffma2(qb.x, xf2, qb.y);
        mlo = fminf(mlo, lo2(cand));
        mhi = fminf(mhi, hi2(cand));
    }

    atomicAdd(&g_S[b*NGT + t], lo2(acc2) + hi2(acc2));

    float m = fminf(mlo, mhi) + xf * xf;          // add x^2 once
    m = fmaxf(m, 1e-12f);                         // cancellation guard
    float cterm = p * sqrt_approx(m);
    float pr = p;
#pragma unroll
    for (int o = 16; o; o >>= 1) {
        cterm += __shfl_down_sync(0xFFFFFFFFu, cterm, o);
        pr    += __shfl_down_sync(0xFFFFFFFFu, pr, o);
    }
    if ((t & 31) == 0) { s_c[t >> 5] = cterm; s_p[t >> 5] = pr; }
    __syncthreads();
    if (t == 0) {
        float C = 0.0f, P = 0.0f;
#pragma unroll
        for (int i = 0; i < 8; i++) { C += s_c[i]; P += s_p[i]; }
        atomicAdd(&g_t1[b], C);
        atomicAdd(&g_np[b], P);
    }

    // ---- completion ticket: release this block's atomics, grab ticket ----
    __threadfence();
    __syncthreads();
    if (t == 0) {
        s_last = (atomicAdd(&g_done, 1u) == (NBLK - 1)) ? 1u : 0u;
    }
    __syncthreads();
    if (s_last == 0u) return;

    // ---- finalize (only the last block) ----
    __threadfence();                 // acquire: all other blocks' atomics visible
    __shared__ float sred[8];
    __shared__ float st1[8];
    const float invA = -1.0f / 9.0f;

    float s = 0.0f;
#pragma unroll
    for (int bb = 0; bb < BB; bb++) {
        float mm = __ldcg(&g_S[bb*NGT + t]) * (1.0f / (float)NPIX);
        s += ex2_approx(lg2_approx(mm) * invA);   // mm^(-1/9)
    }
    if (t < BB) st1[t] = __ldcg(&g_t1[t]) / (__ldcg(&g_np[t]) + EPSF);

#pragma unroll
    for (int o = 16; o; o >>= 1) s += __shfl_down_sync(0xFFFFFFFFu, s, o);
    if ((t & 31) == 0) sred[t >> 5] = s;
    __syncthreads();

    // re-zero scratch + ticket for the next graph replay
#pragma unroll
    for (int bb = 0; bb < BB; bb++) g_S[bb*NGT + t] = 0.0f;
    if (t < BB) { g_t1[t] = 0.0f; g_np[t] = 0.0f; }
    if (t == 0) g_done = 0u;

    if (t == 0) {
        float T2 = 0.0f;
#pragma unroll
        for (int i = 0; i < 8; i++) T2 += sred[i];
        T2 *= (1.0f / (float)(BB * NGT));
        float T1 = 0.0f;
#pragma unroll
        for (int bb = 0; bb < BB; bb++) T1 += st1[bb];
        T1 *= (1.0f / (float)BB);
        out[0] = T1 + T2;
    }
}

// -------------------------------------------------------------------
extern "C" void kernel_launch(void* const* d_in, const int* in_sizes, int n_in,
                              void* d_out, int out_size) {
    const float* prob = (const float*)d_in[0];   // (B,1,H,W) f32
    const float* gt   = (const float*)d_in[1];   // (B,NGT,2) f32
    float* out = (float*)d_out;

    dim3 grid(HH, BB);
    k_fused<<<grid, 256>>>(prob, gt, out);
}